// round 1
// baseline (speedup 1.0000x reference)
#include <cuda_runtime.h>
#include <math.h>

#define M_TOT 3872
#define MPAD  3904
#define EDIM  128
#define HW    16384
#define NPRE  500
#define NPAD  512
#define MAXI  30

// ---------------- device scratch (static globals; no allocation) ----------------
__device__ float    g_scores[MPAD];
__device__ float    g_kernels[MPAD * EDIM];
__device__ unsigned g_masks[MPAD * 512];          // bitpacked seg_masks, 512 words/cell
__device__ float    g_sumpart[MPAD * 8];          // masked-prob partial sums per pixel-chunk
__device__ int      g_cntpart[MPAD * 8];          // mask-count partials per pixel-chunk
__device__ float    g_cscores[MPAD];
__device__ float    g_summask[MPAD];
__device__ float    g_vals500[NPAD];
__device__ int      g_idx500[NPAD];
__device__ float    g_sm500[NPAD];
__device__ float    g_iou[NPAD * NPAD];
__device__ float    g_comp2[NPAD];
__device__ float    g_nms[NPAD];
__device__ float    g_fs30[MAXI];
__device__ int      g_sel30[MAXI];
__device__ float    g_selpred[MAXI * HW];
__device__ int      g_box[MAXI * 4];              // xmin,ymin,xmax,ymax (int, atomics)

struct Ptrs {
    const float* cate[5];
    const float* kern[5];
    const float* seg;
};

// ---------------- init: zero iou, init boxes ----------------
__global__ void init_kernel() {
    int id = blockIdx.x * blockDim.x + threadIdx.x;
    if (id < NPAD * NPAD) g_iou[id] = 0.f;
    if (id < MAXI) {
        g_box[id * 4 + 0] = 512;   // xmin init (min over empty -> ORI_W)
        g_box[id * 4 + 1] = 512;   // ymin
        g_box[id * 4 + 2] = -1;    // xmax
        g_box[id * 4 + 3] = -1;    // ymax
    }
}

// ---------------- gather scores + kernels (transpose per-level) ----------------
__global__ void gather_kernel(Ptrs p) {
    int gid = blockIdx.x * blockDim.x + threadIdx.x;
    if (gid >= M_TOT * EDIM) return;
    int m = gid >> 7;
    int e = gid & 127;
    int l, ml, gg;
    if      (m < 1600) { l = 0; ml = m;        gg = 1600; }
    else if (m < 2896) { l = 1; ml = m - 1600; gg = 1296; }
    else if (m < 3472) { l = 2; ml = m - 2896; gg = 576;  }
    else if (m < 3728) { l = 3; ml = m - 3472; gg = 256;  }
    else               { l = 4; ml = m - 3728; gg = 144;  }
    g_kernels[gid] = p.kern[l][e * gg + ml];
    if (e == 0) g_scores[m] = p.cate[l][ml];
}

// ---------------- fused GEMM + sigmoid + mask/sum reduction ----------------
// grid (8 pixel-chunks, 61 m-tiles), 256 threads.
// Block: 64 cells x 2048 pixels (8 subtiles of 256 px), K=128 in 4 chunks of 32.
__global__ __launch_bounds__(256) void gemm_kernel(const float* __restrict__ seg) {
    __shared__ float As[32][65];      // As[k][cell]
    __shared__ float Bs[32][256];     // Bs[k][pixel]
    int tid = threadIdx.x;
    int tp = tid & 31;                // pixel lane
    int tm = tid >> 5;                // cell-group (warp)
    int cb = tm * 8;
    int m0 = blockIdx.y * 64;
    int pchunk = blockIdx.x;

    float msum[8];
    int   mcnt[8];
#pragma unroll
    for (int i = 0; i < 8; ++i) { msum[i] = 0.f; mcnt[i] = 0; }

    for (int st = 0; st < 8; ++st) {
        int p0 = pchunk * 2048 + st * 256;
        float acc[8][8];
#pragma unroll
        for (int i = 0; i < 8; ++i)
#pragma unroll
            for (int j = 0; j < 8; ++j) acc[i][j] = 0.f;

        for (int kc = 0; kc < 4; ++kc) {
            int k0 = kc * 32;
            for (int t = tid; t < 64 * 32; t += 256) {
                int c = t >> 5, kk = t & 31;
                int m = m0 + c;
                As[kk][c] = (m < M_TOT) ? g_kernels[m * EDIM + k0 + kk] : 0.f;
            }
            for (int t = tid; t < 32 * 256; t += 256) {
                int kk = t >> 8, pp = t & 255;
                Bs[kk][pp] = seg[(k0 + kk) * HW + p0 + pp];
            }
            __syncthreads();
#pragma unroll 4
            for (int kk = 0; kk < 32; ++kk) {
                float a[8], b[8];
#pragma unroll
                for (int i = 0; i < 8; ++i) a[i] = As[kk][cb + i];
#pragma unroll
                for (int j = 0; j < 8; ++j) b[j] = Bs[kk][tp + 32 * j];
#pragma unroll
                for (int i = 0; i < 8; ++i)
#pragma unroll
                    for (int j = 0; j < 8; ++j)
                        acc[i][j] = fmaf(a[i], b[j], acc[i][j]);
            }
            __syncthreads();
        }

        // epilogue: sigmoid, mask bitpack via ballot, per-cell partial sums
#pragma unroll
        for (int i = 0; i < 8; ++i) {
            int m = m0 + cb + i;               // uniform across warp
            float lsum = 0.f;
            int lcnt = 0;
#pragma unroll
            for (int j = 0; j < 8; ++j) {
                float l = acc[i][j];
                float prob = __frcp_rn(1.f + __expf(-l));
                bool mk = prob > 0.5f;
                unsigned w = __ballot_sync(0xffffffffu, mk);
                if (mk) lsum += prob;
                if (tp == 0) {
                    lcnt += __popc(w);
                    if (m < M_TOT) g_masks[m * 512 + (p0 >> 5) + j] = w;
                }
            }
            for (int off = 16; off; off >>= 1)
                lsum += __shfl_down_sync(0xffffffffu, lsum, off);
            if (tp == 0) { msum[i] += lsum; mcnt[i] += lcnt; }
        }
    }
    if (tp == 0) {
#pragma unroll
        for (int i = 0; i < 8; ++i) {
            int m = m0 + cb + i;
            if (m < M_TOT) {
                g_sumpart[m * 8 + pchunk] = msum[i];
                g_cntpart[m * 8 + pchunk] = mcnt[i];
            }
        }
    }
}

// ---------------- cate-score combine ----------------
__global__ void cscore_kernel() {
    int m = blockIdx.x * blockDim.x + threadIdx.x;
    if (m >= M_TOT) return;
    float s = 0.f; int c = 0;
    for (int k = 0; k < 8; ++k) { s += g_sumpart[m * 8 + k]; c += g_cntpart[m * 8 + k]; }
    float cnt = (float)c;
    g_summask[m] = cnt;
    float stride = (m < 1600) ? 4.f : (m < 2896) ? 8.f : (m < 3472) ? 16.f : (m < 3728) ? 32.f : 64.f;
    float score = g_scores[m];
    bool keep = (score > 0.3f) && (cnt > stride);
    float segscore = s / fmaxf(cnt, 1.f);
    g_cscores[m] = keep ? score * segscore : 0.f;
}

// ---------------- top-500 (bitonic over 4096; desc value, asc index) ----------------
__global__ __launch_bounds__(1024) void top500_kernel() {
    __shared__ float sv[4096];
    __shared__ int   si[4096];
    int t = threadIdx.x;
    for (int i = t; i < 4096; i += 1024) {
        if (i < M_TOT) { sv[i] = g_cscores[i]; si[i] = i; }
        else           { sv[i] = -1.f;         si[i] = 1 << 20; }
    }
    __syncthreads();
    for (int k = 2; k <= 4096; k <<= 1) {
        for (int j = k >> 1; j > 0; j >>= 1) {
            for (int i = t; i < 4096; i += 1024) {
                int ixj = i ^ j;
                if (ixj > i) {
                    bool dir = ((i & k) == 0);
                    float v1 = sv[i], v2 = sv[ixj];
                    int  i1 = si[i], i2 = si[ixj];
                    bool before = (v1 > v2) || (v1 == v2 && i1 < i2);
                    if (before != dir) { sv[i] = v2; sv[ixj] = v1; si[i] = i2; si[ixj] = i1; }
                }
            }
            __syncthreads();
        }
    }
    for (int i = t; i < NPAD; i += 1024) {
        g_vals500[i] = sv[i];
        g_idx500[i]  = si[i];
        int cell = si[i];
        g_sm500[i] = (i < NPRE && cell < M_TOT) ? g_summask[cell] : 0.f;
    }
}

// ---------------- pairwise IoU via bitmask popcount ----------------
__global__ __launch_bounds__(256) void nms_inter_kernel() {
    int bi = blockIdx.y, bj = blockIdx.x;
    if (bi > bj) return;
    __shared__ unsigned smI[32][65], smJ[32][65];
    __shared__ int ridxI[32], ridxJ[32];
    int tid = threadIdx.x;
    if (tid < 32)      { int i = bi * 32 + tid;      ridxI[tid]      = (i < NPRE) ? g_idx500[i] : -1; }
    else if (tid < 64) { int t2 = tid - 32; int j = bj * 32 + t2; ridxJ[t2] = (j < NPRE) ? g_idx500[j] : -1; }
    __syncthreads();
    int tj = tid & 31;
    int ti0 = (tid >> 5) * 4;
    int acc[4] = {0, 0, 0, 0};
    for (int w0 = 0; w0 < 512; w0 += 64) {
        for (int t = tid; t < 32 * 64; t += 256) {
            int r = t >> 6, c = t & 63;
            int mi = ridxI[r];
            smI[r][c] = (mi >= 0) ? g_masks[mi * 512 + w0 + c] : 0u;
            int mj = ridxJ[r];
            smJ[r][c] = (mj >= 0) ? g_masks[mj * 512 + w0 + c] : 0u;
        }
        __syncthreads();
#pragma unroll 8
        for (int w = 0; w < 64; ++w) {
            unsigned b = smJ[tj][w];
#pragma unroll
            for (int r = 0; r < 4; ++r) acc[r] += __popc(smI[ti0 + r][w] & b);
        }
        __syncthreads();
    }
#pragma unroll
    for (int r = 0; r < 4; ++r) {
        int i = bi * 32 + ti0 + r;
        int j = bj * 32 + tj;
        if (i < j && j < NPRE) {
            float inter = (float)acc[r];
            float uni = g_sm500[i] + g_sm500[j] - inter;
            g_iou[i * NPAD + j] = inter / fmaxf(uni, 1.f);
        }
    }
}

// ---------------- comp = column max of iou; store comp^2 ----------------
__global__ void comp_kernel() {
    int x = blockIdx.x * blockDim.x + threadIdx.x;
    if (x >= NPAD) return;
    float mx = 0.f;
    for (int r = 0; r < NPRE; ++r) mx = fmaxf(mx, g_iou[r * NPAD + x]);
    g_comp2[x] = mx * mx;
}

// ---------------- matrix-NMS decay ----------------
__global__ void decay_kernel() {
    int j = blockIdx.x * blockDim.x + threadIdx.x;
    if (j >= NPAD) return;
    if (j < NPRE) {
        float mn = 3.4e38f;
        for (int i = 0; i < NPRE; ++i) {
            float v = g_iou[i * NPAD + j];
            mn = fminf(mn, g_comp2[i] - v * v);
        }
        float ns = g_vals500[j] * expf(2.f * mn);
        g_nms[j] = (ns >= 0.05f) ? ns : 0.f;
    } else {
        g_nms[j] = -1.f;
    }
}

// ---------------- top-30 (bitonic over 512) + write scores/vis ----------------
__global__ __launch_bounds__(256) void top30_kernel(float* out) {
    __shared__ float sv[512];
    __shared__ int   si[512];
    int t = threadIdx.x;
    for (int i = t; i < 512; i += 256) { sv[i] = g_nms[i]; si[i] = i; }
    __syncthreads();
    for (int k = 2; k <= 512; k <<= 1) {
        for (int j = k >> 1; j > 0; j >>= 1) {
            for (int i = t; i < 512; i += 256) {
                int ixj = i ^ j;
                if (ixj > i) {
                    bool dir = ((i & k) == 0);
                    float v1 = sv[i], v2 = sv[ixj];
                    int  i1 = si[i], i2 = si[ixj];
                    bool before = (v1 > v2) || (v1 == v2 && i1 < i2);
                    if (before != dir) { sv[i] = v2; sv[ixj] = v1; si[i] = i2; si[ixj] = i1; }
                }
            }
            __syncthreads();
        }
    }
    if (t < MAXI) {
        float v = sv[t];
        g_fs30[t] = v;
        g_sel30[t] = g_idx500[si[t]];
        out[120 + t] = v;                       // final_scores
        out[150 + t] = (v > 0.3f) ? 1.f : 0.f;  // vis
    }
}

// ---------------- recompute fp32 seg_preds for the 30 selected cells ----------------
__global__ __launch_bounds__(256) void selpred_kernel(const float* __restrict__ seg) {
    __shared__ int   sidx[MAXI];
    __shared__ float kv[MAXI][EDIM];
    int tid = threadIdx.x;
    if (tid < MAXI) sidx[tid] = g_sel30[tid];
    __syncthreads();
    for (int t = tid; t < MAXI * EDIM; t += 256) {
        int c = t >> 7, e = t & 127;
        kv[c][e] = g_kernels[sidx[c] * EDIM + e];
    }
    __syncthreads();
    int p = blockIdx.x * 256 + tid;
    float acc[MAXI];
#pragma unroll
    for (int c = 0; c < MAXI; ++c) acc[c] = 0.f;
#pragma unroll 4
    for (int e = 0; e < EDIM; ++e) {
        float s = seg[e * HW + p];
#pragma unroll
        for (int c = 0; c < MAXI; ++c) acc[c] = fmaf(kv[c][e], s, acc[c]);
    }
#pragma unroll
    for (int c = 0; c < MAXI; ++c)
        g_selpred[c * HW + p] = 1.f / (1.f + expf(-acc[c]));
}

// ---------------- bilinear 4x upsample + bbox reduce ----------------
__global__ void box_kernel() {
    int n = blockIdx.x;
    int band = blockIdx.y;      // 8 bands of 64 output rows
    int tid = threadIdx.x;
    const float* sp = g_selpred + n * HW;
    int mnx = 512, mny = 512, mxx = -1, mxy = -1;
    for (int t = 0; t < 128; ++t) {
        int pix = band * 32768 + t * 256 + tid;
        int y = pix >> 9, x = pix & 511;
        float xin = (x + 0.5f) * 0.25f - 0.5f;
        float yin = (y + 0.5f) * 0.25f - 0.5f;
        int x0 = (int)floorf(xin); float fx = xin - (float)x0;
        int y0 = (int)floorf(yin); float fy = yin - (float)y0;
        int x0c = max(x0, 0), x1c = min(x0 + 1, 127);
        int y0c = max(y0, 0), y1c = min(y0 + 1, 127);
        float v00 = sp[y0c * 128 + x0c], v01 = sp[y0c * 128 + x1c];
        float v10 = sp[y1c * 128 + x0c], v11 = sp[y1c * 128 + x1c];
        float v = (1.f - fy) * ((1.f - fx) * v00 + fx * v01)
                +        fy  * ((1.f - fx) * v10 + fx * v11);
        if (v > 0.5f) {
            mnx = min(mnx, x); mxx = max(mxx, x);
            mny = min(mny, y); mxy = max(mxy, y);
        }
    }
    mnx = __reduce_min_sync(0xffffffffu, mnx);
    mny = __reduce_min_sync(0xffffffffu, mny);
    mxx = __reduce_max_sync(0xffffffffu, mxx);
    mxy = __reduce_max_sync(0xffffffffu, mxy);
    if ((tid & 31) == 0) {
        atomicMin(&g_box[n * 4 + 0], mnx);
        atomicMin(&g_box[n * 4 + 1], mny);
        atomicMax(&g_box[n * 4 + 2], mxx);
        atomicMax(&g_box[n * 4 + 3], mxy);
    }
}

// ---------------- finalize boxes (vis gate) ----------------
__global__ void final_kernel(float* out) {
    int t = threadIdx.x;
    if (t >= MAXI) return;
    bool vis = g_fs30[t] > 0.3f;
    out[t * 4 + 0] = vis ? (float)g_box[t * 4 + 0] : 0.f;
    out[t * 4 + 1] = vis ? (float)g_box[t * 4 + 1] : 0.f;
    out[t * 4 + 2] = vis ? (float)g_box[t * 4 + 2] : 0.f;
    out[t * 4 + 3] = vis ? (float)g_box[t * 4 + 3] : 0.f;
}

// ---------------- host launcher ----------------
extern "C" void kernel_launch(void* const* d_in, const int* in_sizes, int n_in,
                              void* d_out, int out_size) {
    (void)out_size;
    Ptrs p;
    // setup_inputs builds the dict interleaved (cate0, kern0, cate1, ...). Detect
    // layout from sizes to be robust: kern0 has 204800 elems, cate1 has 1296.
    if (n_in >= 11 && in_sizes[1] == 204800) {
        for (int i = 0; i < 5; ++i) {
            p.cate[i] = (const float*)d_in[2 * i];
            p.kern[i] = (const float*)d_in[2 * i + 1];
        }
    } else {
        for (int i = 0; i < 5; ++i) {
            p.cate[i] = (const float*)d_in[i];
            p.kern[i] = (const float*)d_in[5 + i];
        }
    }
    p.seg = (const float*)d_in[10];
    float* out = (float*)d_out;

    init_kernel<<<1024, 256>>>();
    gather_kernel<<<(M_TOT * EDIM + 255) / 256, 256>>>(p);
    gemm_kernel<<<dim3(8, 61), 256>>>(p.seg);
    cscore_kernel<<<16, 256>>>();
    top500_kernel<<<1, 1024>>>();
    nms_inter_kernel<<<dim3(16, 16), 256>>>();
    comp_kernel<<<2, 256>>>();
    decay_kernel<<<2, 256>>>();
    top30_kernel<<<1, 256>>>(out);
    selpred_kernel<<<64, 256>>>(p.seg);
    box_kernel<<<dim3(30, 8), 256>>>();
    final_kernel<<<1, 32>>>(out);
}

// round 2
// speedup vs baseline: 1.1849x; 1.1849x over previous
#include <cuda_runtime.h>
#include <math.h>

#define M_TOT 3872
#define MPAD  3904
#define EDIM  128
#define HW    16384
#define NPRE  500
#define NPAD  512
#define MAXI  30

// ---------------- device scratch (static globals; no allocation) ----------------
__device__ int      g_count;
__device__ int      g_orig[MPAD];                 // compact idx -> original cell id
__device__ float    g_scores[MPAD];               // compact scores
__device__ float    g_kernels[MPAD * EDIM];       // compact [c][e]
__device__ float    g_kernelsT[EDIM * MPAD];      // compact [e][c]
__device__ unsigned g_masks[4096 * 512];          // bitpacked seg_masks, 512 words/cell
__device__ float    g_sumpart[MPAD * 8];
__device__ int      g_cntpart[MPAD * 8];
__device__ float    g_cscores[4096];
__device__ float    g_summask[4096];
__device__ float    g_vals500[NPAD];
__device__ int      g_idx500[NPAD];
__device__ float    g_sm500[NPAD];
__device__ float    g_iou[NPAD * NPAD];           // TRANSPOSED: [j][i] = iou(i,j), i<j
__device__ float    g_comp2[NPAD];
__device__ float    g_nms[NPAD];
__device__ float    g_fs30[MAXI];
__device__ int      g_sel30[MAXI];
__device__ float    g_selpred[MAXI * HW];
__device__ int      g_box[MAXI * 4];

struct Ptrs {
    const float* cate[5];
    const float* kern[5];
    const float* seg;
};

__device__ __forceinline__ void cell_level(int m, int& l, int& ml, int& gg) {
    if      (m < 1600) { l = 0; ml = m;        gg = 1600; }
    else if (m < 2896) { l = 1; ml = m - 1600; gg = 1296; }
    else if (m < 3472) { l = 2; ml = m - 2896; gg = 576;  }
    else if (m < 3728) { l = 3; ml = m - 3472; gg = 256;  }
    else               { l = 4; ml = m - 3728; gg = 144;  }
}

// ---------------- init: zero iou, init boxes ----------------
__global__ void init_kernel() {
    int id = blockIdx.x * blockDim.x + threadIdx.x;
    if (id < NPAD * NPAD) g_iou[id] = 0.f;
    if (id < MAXI) {
        g_box[id * 4 + 0] = 512;
        g_box[id * 4 + 1] = 512;
        g_box[id * 4 + 2] = -1;
        g_box[id * 4 + 3] = -1;
    }
}

// ---------------- deterministic compaction of cells with score > 0.3 ----------------
__global__ __launch_bounds__(1024) void compact_kernel(Ptrs p) {
    __shared__ int wsum[32];
    int t = threadIdx.x;
    float sc[4]; int vf[4]; int cnt = 0;
#pragma unroll
    for (int r = 0; r < 4; ++r) {
        int m = t * 4 + r;
        float s = 0.f; int v = 0;
        if (m < M_TOT) {
            int l, ml, gg; cell_level(m, l, ml, gg);
            s = p.cate[l][ml];
            v = (s > 0.3f) ? 1 : 0;
        }
        sc[r] = s; vf[r] = v; cnt += v;
    }
    int lane = t & 31, warp = t >> 5;
    int x = cnt;
#pragma unroll
    for (int off = 1; off < 32; off <<= 1) {
        int y = __shfl_up_sync(0xffffffffu, x, off);
        if (lane >= off) x += y;
    }
    if (lane == 31) wsum[warp] = x;
    __syncthreads();
    if (warp == 0) {
        int w = wsum[lane];
#pragma unroll
        for (int off = 1; off < 32; off <<= 1) {
            int y = __shfl_up_sync(0xffffffffu, w, off);
            if (lane >= off) w += y;
        }
        wsum[lane] = w;
        if (lane == 31) g_count = w;
    }
    __syncthreads();
    int base = (warp ? wsum[warp - 1] : 0) + x - cnt;
#pragma unroll
    for (int r = 0; r < 4; ++r) {
        if (vf[r]) {
            g_orig[base] = t * 4 + r;
            g_scores[base] = sc[r];
            base++;
        }
    }
}

// ---------------- gather kernels (compact, both layouts) ----------------
__global__ void gather_kernel(Ptrs p) {
    int gid = blockIdx.x * blockDim.x + threadIdx.x;
    if (gid >= MPAD * EDIM) return;
    int c = gid >> 7;
    int e = gid & 127;
    if (c >= g_count) return;
    int m = g_orig[c];
    int l, ml, gg; cell_level(m, l, ml, gg);
    float v = p.kern[l][e * gg + ml];
    g_kernels[c * EDIM + e] = v;
    g_kernelsT[e * MPAD + c] = v;
}

// ---------------- fused GEMM (f32x2) + sigmoid + mask/sum reduction ----------------
// grid (8 pixel-chunks, 61 m-tiles), 256 threads.
// Block: 64 cells x 2048 pixels (8 subtiles of 256 px), K=128 in 4 chunks of 32.
// Pixel pairs packed as (p, p+32) so ballots produce mask words directly.
__global__ __launch_bounds__(256, 2) void gemm_kernel(const float* __restrict__ seg) {
    __shared__ float2 As2[32][64];     // duplicated (a,a) per cell
    __shared__ float  Bsf[32][256];    // permuted pixel pairs
    int Mc = g_count;
    int m0 = blockIdx.y * 64;
    if (m0 >= Mc) return;
    int tid = threadIdx.x;
    int tp = tid & 31;
    int tm = tid >> 5;
    int cb = tm * 8;
    int pchunk = blockIdx.x;

    float msum[8]; int mcnt[8];
#pragma unroll
    for (int i = 0; i < 8; ++i) { msum[i] = 0.f; mcnt[i] = 0; }

    const unsigned long long* Au = reinterpret_cast<const unsigned long long*>(&As2[0][0]);
    const unsigned long long* Bu = reinterpret_cast<const unsigned long long*>(&Bsf[0][0]);

    for (int st = 0; st < 8; ++st) {
        int p0 = pchunk * 2048 + st * 256;
        unsigned long long acc[8][4];
#pragma unroll
        for (int i = 0; i < 8; ++i)
#pragma unroll
            for (int j = 0; j < 4; ++j) acc[i][j] = 0ULL;

        for (int kc = 0; kc < 4; ++kc) {
            int k0 = kc * 32;
            // A fill: coalesced LDG, conflict-free STS.64
            for (int t = tid; t < 2048; t += 256) {
                int kk = t >> 6, c = t & 63;
                float v = (m0 + c < Mc) ? g_kernelsT[(k0 + kk) * MPAD + m0 + c] : 0.f;
                As2[kk][c] = make_float2(v, v);
            }
            // B fill: pair-permute pixels -> slot holds (p, p+32) of its 64-group
            for (int t = tid; t < 8192; t += 256) {
                int kk = t >> 8, pp = t & 255;
                float v = seg[(k0 + kk) * HW + p0 + pp];
                int g = pp >> 6, w = pp & 63;
                Bsf[kk][g * 64 + (w & 31) * 2 + (w >> 5)] = v;
            }
            __syncthreads();
#pragma unroll 4
            for (int kk = 0; kk < 32; ++kk) {
                unsigned long long a[8], b[4];
#pragma unroll
                for (int i = 0; i < 8; ++i) a[i] = Au[kk * 64 + cb + i];
#pragma unroll
                for (int j = 0; j < 4; ++j) b[j] = Bu[kk * 128 + j * 32 + tp];
#pragma unroll
                for (int i = 0; i < 8; ++i)
#pragma unroll
                    for (int j = 0; j < 4; ++j)
                        asm("fma.rn.f32x2 %0, %1, %2, %0;"
                            : "+l"(acc[i][j]) : "l"(a[i]), "l"(b[j]));
            }
            __syncthreads();
        }

        // epilogue: sigmoid, mask bitpack (x-> word 2j, y-> word 2j+1), partial sums
#pragma unroll
        for (int i = 0; i < 8; ++i) {
            int m = m0 + cb + i;
            float lsum = 0.f;
            int lcnt = 0;
#pragma unroll
            for (int j = 0; j < 4; ++j) {
                float2 v = *reinterpret_cast<float2*>(&acc[i][j]);
                float px = __frcp_rn(1.f + __expf(-v.x));
                float py = __frcp_rn(1.f + __expf(-v.y));
                bool mx = px > 0.5f, my = py > 0.5f;
                unsigned wx = __ballot_sync(0xffffffffu, mx);
                unsigned wy = __ballot_sync(0xffffffffu, my);
                if (mx) lsum += px;
                if (my) lsum += py;
                if (tp == 0) {
                    lcnt += __popc(wx) + __popc(wy);
                    if (m < Mc) {
                        g_masks[m * 512 + (p0 >> 5) + 2 * j]     = wx;
                        g_masks[m * 512 + (p0 >> 5) + 2 * j + 1] = wy;
                    }
                }
            }
            for (int off = 16; off; off >>= 1)
                lsum += __shfl_down_sync(0xffffffffu, lsum, off);
            if (tp == 0) { msum[i] += lsum; mcnt[i] += lcnt; }
        }
    }
    if (tp == 0) {
#pragma unroll
        for (int i = 0; i < 8; ++i) {
            int m = m0 + cb + i;
            if (m < Mc) {
                g_sumpart[m * 8 + pchunk] = msum[i];
                g_cntpart[m * 8 + pchunk] = mcnt[i];
            }
        }
    }
}

// ---------------- cate-score combine (compact domain, sentinel padding) ----------------
__global__ void cscore_kernel() {
    int m = blockIdx.x * blockDim.x + threadIdx.x;
    if (m >= 4096) return;
    int Mc = g_count;
    if (m >= Mc) { g_cscores[m] = -1.f; g_summask[m] = 0.f; return; }
    float s = 0.f; int c = 0;
    for (int k = 0; k < 8; ++k) { s += g_sumpart[m * 8 + k]; c += g_cntpart[m * 8 + k]; }
    float cnt = (float)c;
    g_summask[m] = cnt;
    int om = g_orig[m];
    float stride = (om < 1600) ? 4.f : (om < 2896) ? 8.f : (om < 3472) ? 16.f : (om < 3728) ? 32.f : 64.f;
    bool keep = cnt > stride;    // score > 0.3 guaranteed by compaction
    float segscore = s / fmaxf(cnt, 1.f);
    g_cscores[m] = keep ? g_scores[m] * segscore : 0.f;
}

// ---------------- top-500 (bitonic over 4096; desc value, asc index) ----------------
__global__ __launch_bounds__(1024) void top500_kernel() {
    __shared__ float sv[4096];
    __shared__ int   si[4096];
    int t = threadIdx.x;
    for (int i = t; i < 4096; i += 1024) { sv[i] = g_cscores[i]; si[i] = i; }
    __syncthreads();
    for (int k = 2; k <= 4096; k <<= 1) {
        for (int j = k >> 1; j > 0; j >>= 1) {
            for (int i = t; i < 4096; i += 1024) {
                int ixj = i ^ j;
                if (ixj > i) {
                    bool dir = ((i & k) == 0);
                    float v1 = sv[i], v2 = sv[ixj];
                    int  i1 = si[i], i2 = si[ixj];
                    bool before = (v1 > v2) || (v1 == v2 && i1 < i2);
                    if (before != dir) { sv[i] = v2; sv[ixj] = v1; si[i] = i2; si[ixj] = i1; }
                }
            }
            __syncthreads();
        }
    }
    int Mc = g_count;
    for (int i = t; i < NPAD; i += 1024) {
        g_vals500[i] = sv[i];
        g_idx500[i]  = si[i];
        int cell = si[i];
        g_sm500[i] = (i < NPRE && cell < Mc) ? g_summask[cell] : 0.f;
    }
}

// ---------------- pairwise IoU via bitmask popcount (writes TRANSPOSED) ----------------
__global__ __launch_bounds__(256) void nms_inter_kernel() {
    int bi = blockIdx.y, bj = blockIdx.x;
    if (bi > bj) return;
    __shared__ unsigned smI[32][65], smJ[32][65];
    __shared__ int ridxI[32], ridxJ[32];
    int tid = threadIdx.x;
    if (tid < 32)      { int i = bi * 32 + tid;      ridxI[tid] = (i < NPRE) ? g_idx500[i] : -1; }
    else if (tid < 64) { int t2 = tid - 32; int j = bj * 32 + t2; ridxJ[t2] = (j < NPRE) ? g_idx500[j] : -1; }
    __syncthreads();
    int tj = tid & 31;
    int ti0 = (tid >> 5) * 4;
    int acc[4] = {0, 0, 0, 0};
    for (int w0 = 0; w0 < 512; w0 += 64) {
        for (int t = tid; t < 32 * 64; t += 256) {
            int r = t >> 6, c = t & 63;
            int mi = ridxI[r];
            smI[r][c] = (mi >= 0) ? g_masks[mi * 512 + w0 + c] : 0u;
            int mj = ridxJ[r];
            smJ[r][c] = (mj >= 0) ? g_masks[mj * 512 + w0 + c] : 0u;
        }
        __syncthreads();
#pragma unroll 8
        for (int w = 0; w < 64; ++w) {
            unsigned b = smJ[tj][w];
#pragma unroll
            for (int r = 0; r < 4; ++r) acc[r] += __popc(smI[ti0 + r][w] & b);
        }
        __syncthreads();
    }
#pragma unroll
    for (int r = 0; r < 4; ++r) {
        int i = bi * 32 + ti0 + r;
        int j = bj * 32 + tj;
        if (i < j && j < NPRE) {
            float inter = (float)acc[r];
            float uni = g_sm500[i] + g_sm500[j] - inter;
            g_iou[j * NPAD + i] = inter / fmaxf(uni, 1.f);   // transposed store
        }
    }
}

// ---------------- comp2[x] = (max_i iou[i][x])^2 : coalesced row-max over iouT ----------------
__global__ __launch_bounds__(256) void comp_kernel() {
    int warp = threadIdx.x >> 5, lane = threadIdx.x & 31;
    int x = blockIdx.x * 8 + warp;
    if (x >= NPAD) return;
    float mx = 0.f;
    for (int i = lane; i < NPAD; i += 32) mx = fmaxf(mx, g_iou[x * NPAD + i]);
    for (int off = 16; off; off >>= 1)
        mx = fmaxf(mx, __shfl_down_sync(0xffffffffu, mx, off));
    if (lane == 0) g_comp2[x] = mx * mx;
}

// ---------------- matrix-NMS decay: coalesced row-min over iouT ----------------
__global__ __launch_bounds__(256) void decay_kernel() {
    int warp = threadIdx.x >> 5, lane = threadIdx.x & 31;
    int j = blockIdx.x * 8 + warp;
    if (j >= NPAD) return;
    if (j >= NPRE) { if (lane == 0) g_nms[j] = -1.f; return; }
    float mn = 3.4e38f;
    for (int i = lane; i < NPRE; i += 32) {
        float v = g_iou[j * NPAD + i];
        mn = fminf(mn, g_comp2[i] - v * v);
    }
    for (int off = 16; off; off >>= 1)
        mn = fminf(mn, __shfl_down_sync(0xffffffffu, mn, off));
    if (lane == 0) {
        float ns = g_vals500[j] * expf(2.f * mn);
        g_nms[j] = (ns >= 0.05f) ? ns : 0.f;
    }
}

// ---------------- top-30 (bitonic over 512) + write scores/vis ----------------
__global__ __launch_bounds__(256) void top30_kernel(float* out) {
    __shared__ float sv[512];
    __shared__ int   si[512];
    int t = threadIdx.x;
    for (int i = t; i < 512; i += 256) { sv[i] = g_nms[i]; si[i] = i; }
    __syncthreads();
    for (int k = 2; k <= 512; k <<= 1) {
        for (int j = k >> 1; j > 0; j >>= 1) {
            for (int i = t; i < 512; i += 256) {
                int ixj = i ^ j;
                if (ixj > i) {
                    bool dir = ((i & k) == 0);
                    float v1 = sv[i], v2 = sv[ixj];
                    int  i1 = si[i], i2 = si[ixj];
                    bool before = (v1 > v2) || (v1 == v2 && i1 < i2);
                    if (before != dir) { sv[i] = v2; sv[ixj] = v1; si[i] = i2; si[ixj] = i1; }
                }
            }
            __syncthreads();
        }
    }
    if (t < MAXI) {
        float v = sv[t];
        g_fs30[t] = v;
        int id = g_idx500[si[t]];
        if (id < 0 || id >= MPAD) id = 0;     // defensive clamp (unreachable in practice)
        g_sel30[t] = id;
        out[120 + t] = v;
        out[150 + t] = (v > 0.3f) ? 1.f : 0.f;
    }
}

// ---------------- recompute fp32 seg_preds for the 30 selected cells ----------------
__global__ __launch_bounds__(256) void selpred_kernel(const float* __restrict__ seg) {
    __shared__ int   sidx[MAXI];
    __shared__ float kv[MAXI][EDIM];
    int tid = threadIdx.x;
    if (tid < MAXI) sidx[tid] = g_sel30[tid];
    __syncthreads();
    for (int t = tid; t < MAXI * EDIM; t += 256) {
        int c = t >> 7, e = t & 127;
        kv[c][e] = g_kernels[sidx[c] * EDIM + e];
    }
    __syncthreads();
    int p = blockIdx.x * 256 + tid;
    float acc[MAXI];
#pragma unroll
    for (int c = 0; c < MAXI; ++c) acc[c] = 0.f;
#pragma unroll 4
    for (int e = 0; e < EDIM; ++e) {
        float s = seg[e * HW + p];
#pragma unroll
        for (int c = 0; c < MAXI; ++c) acc[c] = fmaf(kv[c][e], s, acc[c]);
    }
#pragma unroll
    for (int c = 0; c < MAXI; ++c)
        g_selpred[c * HW + p] = 1.f / (1.f + expf(-acc[c]));
}

// ---------------- bilinear 4x upsample + bbox reduce ----------------
__global__ void box_kernel() {
    int n = blockIdx.x;
    int band = blockIdx.y;
    int tid = threadIdx.x;
    const float* sp = g_selpred + n * HW;
    int mnx = 512, mny = 512, mxx = -1, mxy = -1;
    for (int t = 0; t < 128; ++t) {
        int pix = band * 32768 + t * 256 + tid;
        int y = pix >> 9, x = pix & 511;
        float xin = (x + 0.5f) * 0.25f - 0.5f;
        float yin = (y + 0.5f) * 0.25f - 0.5f;
        int x0 = (int)floorf(xin); float fx = xin - (float)x0;
        int y0 = (int)floorf(yin); float fy = yin - (float)y0;
        int x0c = max(x0, 0), x1c = min(x0 + 1, 127);
        int y0c = max(y0, 0), y1c = min(y0 + 1, 127);
        float v00 = sp[y0c * 128 + x0c], v01 = sp[y0c * 128 + x1c];
        float v10 = sp[y1c * 128 + x0c], v11 = sp[y1c * 128 + x1c];
        float v = (1.f - fy) * ((1.f - fx) * v00 + fx * v01)
                +        fy  * ((1.f - fx) * v10 + fx * v11);
        if (v > 0.5f) {
            mnx = min(mnx, x); mxx = max(mxx, x);
            mny = min(mny, y); mxy = max(mxy, y);
        }
    }
    mnx = __reduce_min_sync(0xffffffffu, mnx);
    mny = __reduce_min_sync(0xffffffffu, mny);
    mxx = __reduce_max_sync(0xffffffffu, mxx);
    mxy = __reduce_max_sync(0xffffffffu, mxy);
    if ((tid & 31) == 0) {
        atomicMin(&g_box[n * 4 + 0], mnx);
        atomicMin(&g_box[n * 4 + 1], mny);
        atomicMax(&g_box[n * 4 + 2], mxx);
        atomicMax(&g_box[n * 4 + 3], mxy);
    }
}

// ---------------- finalize boxes (vis gate) ----------------
__global__ void final_kernel(float* out) {
    int t = threadIdx.x;
    if (t >= MAXI) return;
    bool vis = g_fs30[t] > 0.3f;
    out[t * 4 + 0] = vis ? (float)g_box[t * 4 + 0] : 0.f;
    out[t * 4 + 1] = vis ? (float)g_box[t * 4 + 1] : 0.f;
    out[t * 4 + 2] = vis ? (float)g_box[t * 4 + 2] : 0.f;
    out[t * 4 + 3] = vis ? (float)g_box[t * 4 + 3] : 0.f;
}

// ---------------- host launcher ----------------
extern "C" void kernel_launch(void* const* d_in, const int* in_sizes, int n_in,
                              void* d_out, int out_size) {
    (void)out_size;
    Ptrs p;
    if (n_in >= 11 && in_sizes[1] == 204800) {
        for (int i = 0; i < 5; ++i) {
            p.cate[i] = (const float*)d_in[2 * i];
            p.kern[i] = (const float*)d_in[2 * i + 1];
        }
    } else {
        for (int i = 0; i < 5; ++i) {
            p.cate[i] = (const float*)d_in[i];
            p.kern[i] = (const float*)d_in[5 + i];
        }
    }
    p.seg = (const float*)d_in[10];
    float* out = (float*)d_out;

    init_kernel<<<1024, 256>>>();
    compact_kernel<<<1, 1024>>>(p);
    gather_kernel<<<(MPAD * EDIM + 255) / 256, 256>>>(p);
    gemm_kernel<<<dim3(8, 61), 256>>>(p.seg);
    cscore_kernel<<<16, 256>>>();
    top500_kernel<<<1, 1024>>>();
    nms_inter_kernel<<<dim3(16, 16), 256>>>();
    comp_kernel<<<64, 256>>>();
    decay_kernel<<<64, 256>>>();
    top30_kernel<<<1, 256>>>(out);
    selpred_kernel<<<64, 256>>>(p.seg);
    box_kernel<<<dim3(30, 8), 256>>>();
    final_kernel<<<1, 32>>>(out);
}

// round 3
// speedup vs baseline: 1.8372x; 1.5505x over previous
#include <cuda_runtime.h>
#include <math.h>

#define M_TOT 3872
#define MPAD  3904
#define EDIM  128
#define HW    16384
#define NPRE  500
#define NPAD  512
#define MAXI  30
#define NCHUNK 64            // pixel chunks of 256

// ---------------- device scratch ----------------
__device__ int      g_count;
__device__ int      g_orig[MPAD];
__device__ float    g_scores[MPAD];
__device__ float    g_kernels[MPAD * EDIM];       // compact [c][e]
__device__ float    g_kernelsT[EDIM * MPAD];      // compact [e][c]
__device__ unsigned g_masks[4096 * 512];
__device__ float    g_sumpart[MPAD * NCHUNK];
__device__ int      g_cntpart[MPAD * NCHUNK];
__device__ float    g_cscores[4096];
__device__ float    g_summask[4096];
__device__ float    g_vals500[NPAD];
__device__ int      g_idx500[NPAD];
__device__ float    g_sm500[NPAD];
__device__ float    g_iou[NPAD * NPAD];           // transposed [j][i]
__device__ float    g_comp2[NPAD];
__device__ float    g_nms[NPAD];
__device__ float    g_fs30[MAXI];
__device__ int      g_sel30[MAXI];
__device__ float    g_selpred[MAXI * HW];
__device__ int      g_box[MAXI * 4];

struct Ptrs {
    const float* cate[5];
    const float* kern[5];
    const float* seg;
};

__device__ __forceinline__ void cell_level(int m, int& l, int& ml, int& gg) {
    if      (m < 1600) { l = 0; ml = m;        gg = 1600; }
    else if (m < 2896) { l = 1; ml = m - 1600; gg = 1296; }
    else if (m < 3472) { l = 2; ml = m - 2896; gg = 576;  }
    else if (m < 3728) { l = 3; ml = m - 3472; gg = 256;  }
    else               { l = 4; ml = m - 3728; gg = 144;  }
}

__device__ __forceinline__ void cp16(void* s, const void* g) {
    unsigned sa = (unsigned)__cvta_generic_to_shared(s);
    asm volatile("cp.async.ca.shared.global [%0], [%1], 16;" :: "r"(sa), "l"(g));
}
__device__ __forceinline__ void cp_commit() { asm volatile("cp.async.commit_group;"); }
template<int N> __device__ __forceinline__ void cp_wait() {
    asm volatile("cp.async.wait_group %0;" :: "n"(N));
}

// ---------------- init ----------------
__global__ void init_kernel() {
    int id = blockIdx.x * blockDim.x + threadIdx.x;
    if (id < NPAD * NPAD) g_iou[id] = 0.f;
    if (id < MAXI) {
        g_box[id * 4 + 0] = 512;
        g_box[id * 4 + 1] = 512;
        g_box[id * 4 + 2] = -1;
        g_box[id * 4 + 3] = -1;
    }
}

// ---------------- deterministic compaction (score > 0.3) ----------------
__global__ __launch_bounds__(1024) void compact_kernel(Ptrs p) {
    __shared__ int wsum[32];
    int t = threadIdx.x;
    float sc[4]; int vf[4]; int cnt = 0;
#pragma unroll
    for (int r = 0; r < 4; ++r) {
        int m = t * 4 + r;
        float s = 0.f; int v = 0;
        if (m < M_TOT) {
            int l, ml, gg; cell_level(m, l, ml, gg);
            s = p.cate[l][ml];
            v = (s > 0.3f) ? 1 : 0;
        }
        sc[r] = s; vf[r] = v; cnt += v;
    }
    int lane = t & 31, warp = t >> 5;
    int x = cnt;
#pragma unroll
    for (int off = 1; off < 32; off <<= 1) {
        int y = __shfl_up_sync(0xffffffffu, x, off);
        if (lane >= off) x += y;
    }
    if (lane == 31) wsum[warp] = x;
    __syncthreads();
    if (warp == 0) {
        int w = wsum[lane];
#pragma unroll
        for (int off = 1; off < 32; off <<= 1) {
            int y = __shfl_up_sync(0xffffffffu, w, off);
            if (lane >= off) w += y;
        }
        wsum[lane] = w;
        if (lane == 31) g_count = w;
    }
    __syncthreads();
    int base = (warp ? wsum[warp - 1] : 0) + x - cnt;
#pragma unroll
    for (int r = 0; r < 4; ++r) {
        if (vf[r]) {
            g_orig[base] = t * 4 + r;
            g_scores[base] = sc[r];
            base++;
        }
    }
}

// ---------------- gather kernels (compact, both layouts) ----------------
__global__ void gather_kernel(Ptrs p) {
    int gid = blockIdx.x * blockDim.x + threadIdx.x;
    if (gid >= MPAD * EDIM) return;
    int c = gid >> 7;
    int e = gid & 127;
    if (c >= g_count) return;
    int m = g_orig[c];
    int l, ml, gg; cell_level(m, l, ml, gg);
    float v = p.kern[l][e * gg + ml];
    g_kernels[c * EDIM + e] = v;
    g_kernelsT[e * MPAD + c] = v;
}

// ---------------- fused GEMM (f32x2, cp.async pipelined) ----------------
// grid (64 chunks of 256 px, 61 m-tiles), 256 threads, 96KB dyn smem.
// A resident [128][64] f32 (32KB). B double-buffered [2][32][256] (64KB).
// Lane tp owns pixel pair (2tp, 2tp+1) within each 64-px group j.
__global__ __launch_bounds__(256, 2) void gemm_kernel(const float* __restrict__ seg) {
    extern __shared__ float smem[];
    float* Asm = smem;                 // [128][64]
    float* Bsm[2] = { smem + 8192, smem + 16384 };

    int Mc = g_count;
    int m0 = blockIdx.y * 64;
    if (m0 >= Mc) return;
    int tid = threadIdx.x;
    int tp = tid & 31;
    int tm = tid >> 5;
    int cb = tm * 8;
    int pchunk = blockIdx.x;
    int p0 = pchunk * 256;

    // prologue fills: A (once) + B(kc=0) as group G0
#pragma unroll
    for (int r = 0; r < 8; ++r) {
        int t = tid + r * 256;
        int k = t >> 4, c4 = (t & 15) << 2;
        cp16(Asm + k * 64 + c4, &g_kernelsT[k * MPAD + m0 + c4]);
    }
#pragma unroll
    for (int r = 0; r < 8; ++r) {
        int t = tid + r * 256;
        int kk = t >> 6, f4 = (t & 63) << 2;
        cp16(Bsm[0] + kk * 256 + f4, seg + kk * HW + p0 + f4);
    }
    cp_commit();

    unsigned long long acc[8][4];
#pragma unroll
    for (int i = 0; i < 8; ++i)
#pragma unroll
        for (int j = 0; j < 4; ++j) acc[i][j] = 0ULL;

    for (int kc = 0; kc < 4; ++kc) {
        __syncthreads();                       // prev compute done before refill
        if (kc < 3) {
#pragma unroll
            for (int r = 0; r < 8; ++r) {
                int t = tid + r * 256;
                int kk = t >> 6, f4 = (t & 63) << 2;
                cp16(Bsm[(kc + 1) & 1] + kk * 256 + f4,
                     seg + ((kc + 1) * 32 + kk) * HW + p0 + f4);
            }
            cp_commit();
            cp_wait<1>();                      // G(kc) done, G(kc+1) in flight
        } else {
            cp_wait<0>();
        }
        __syncthreads();

        const float* Bp = Bsm[kc & 1];
#pragma unroll 4
        for (int kk = 0; kk < 32; ++kk) {
            const float* ar = Asm + (kc * 32 + kk) * 64 + cb;
            float4 aA = *reinterpret_cast<const float4*>(ar);
            float4 aB = *reinterpret_cast<const float4*>(ar + 4);
            unsigned long long a64[8];
            asm("mov.b64 %0,{%1,%1};" : "=l"(a64[0]) : "f"(aA.x));
            asm("mov.b64 %0,{%1,%1};" : "=l"(a64[1]) : "f"(aA.y));
            asm("mov.b64 %0,{%1,%1};" : "=l"(a64[2]) : "f"(aA.z));
            asm("mov.b64 %0,{%1,%1};" : "=l"(a64[3]) : "f"(aA.w));
            asm("mov.b64 %0,{%1,%1};" : "=l"(a64[4]) : "f"(aB.x));
            asm("mov.b64 %0,{%1,%1};" : "=l"(a64[5]) : "f"(aB.y));
            asm("mov.b64 %0,{%1,%1};" : "=l"(a64[6]) : "f"(aB.z));
            asm("mov.b64 %0,{%1,%1};" : "=l"(a64[7]) : "f"(aB.w));
            unsigned long long b64[4];
#pragma unroll
            for (int j = 0; j < 4; ++j)
                b64[j] = *reinterpret_cast<const unsigned long long*>(
                    Bp + kk * 256 + j * 64 + tp * 2);
#pragma unroll
            for (int i = 0; i < 8; ++i)
#pragma unroll
                for (int j = 0; j < 4; ++j)
                    asm("fma.rn.f32x2 %0, %1, %2, %0;"
                        : "+l"(acc[i][j]) : "l"(a64[i]), "l"(b64[j]));
        }
    }

    // epilogue: sigmoid, bitpack (even-pixel word, odd-pixel word), per-cell sums
#pragma unroll
    for (int i = 0; i < 8; ++i) {
        int m = m0 + cb + i;
        float lsum = 0.f;
        int lcnt = 0;
#pragma unroll
        for (int j = 0; j < 4; ++j) {
            float2 v = *reinterpret_cast<float2*>(&acc[i][j]);
            float px = __frcp_rn(1.f + __expf(-v.x));
            float py = __frcp_rn(1.f + __expf(-v.y));
            bool mx = px > 0.5f, my = py > 0.5f;
            unsigned wx = __ballot_sync(0xffffffffu, mx);
            unsigned wy = __ballot_sync(0xffffffffu, my);
            if (mx) lsum += px;
            if (my) lsum += py;
            if (tp == 0) {
                lcnt += __popc(wx) + __popc(wy);
                if (m < Mc) {
                    g_masks[m * 512 + pchunk * 8 + 2 * j]     = wx;
                    g_masks[m * 512 + pchunk * 8 + 2 * j + 1] = wy;
                }
            }
        }
        for (int off = 16; off; off >>= 1)
            lsum += __shfl_down_sync(0xffffffffu, lsum, off);
        if (tp == 0 && m < Mc) {
            g_sumpart[m * NCHUNK + pchunk] = lsum;
            g_cntpart[m * NCHUNK + pchunk] = lcnt;
        }
    }
}

// ---------------- cate-score combine ----------------
__global__ void cscore_kernel() {
    int m = blockIdx.x * blockDim.x + threadIdx.x;
    if (m >= 4096) return;
    int Mc = g_count;
    if (m >= Mc) { g_cscores[m] = -1.f; g_summask[m] = 0.f; return; }
    float s = 0.f; int c = 0;
    for (int k = 0; k < NCHUNK; ++k) {
        s += g_sumpart[m * NCHUNK + k];
        c += g_cntpart[m * NCHUNK + k];
    }
    float cnt = (float)c;
    g_summask[m] = cnt;
    int om = g_orig[m];
    float stride = (om < 1600) ? 4.f : (om < 2896) ? 8.f : (om < 3472) ? 16.f : (om < 3728) ? 32.f : 64.f;
    bool keep = cnt > stride;
    float segscore = s / fmaxf(cnt, 1.f);
    g_cscores[m] = keep ? g_scores[m] * segscore : 0.f;
}

// ---------------- top-500 (bitonic over 4096) ----------------
__global__ __launch_bounds__(1024) void top500_kernel() {
    __shared__ float sv[4096];
    __shared__ int   si[4096];
    int t = threadIdx.x;
    for (int i = t; i < 4096; i += 1024) { sv[i] = g_cscores[i]; si[i] = i; }
    __syncthreads();
    for (int k = 2; k <= 4096; k <<= 1) {
        for (int j = k >> 1; j > 0; j >>= 1) {
            for (int i = t; i < 4096; i += 1024) {
                int ixj = i ^ j;
                if (ixj > i) {
                    bool dir = ((i & k) == 0);
                    float v1 = sv[i], v2 = sv[ixj];
                    int  i1 = si[i], i2 = si[ixj];
                    bool before = (v1 > v2) || (v1 == v2 && i1 < i2);
                    if (before != dir) { sv[i] = v2; sv[ixj] = v1; si[i] = i2; si[ixj] = i1; }
                }
            }
            __syncthreads();
        }
    }
    int Mc = g_count;
    for (int i = t; i < NPAD; i += 1024) {
        g_vals500[i] = sv[i];
        g_idx500[i]  = si[i];
        int cell = si[i];
        g_sm500[i] = (i < NPRE && cell < Mc) ? g_summask[cell] : 0.f;
    }
}

// ---------------- pairwise IoU via bitmask popcount (transposed store) ----------------
__global__ __launch_bounds__(256) void nms_inter_kernel() {
    int bi = blockIdx.y, bj = blockIdx.x;
    if (bi > bj) return;
    __shared__ unsigned smI[32][65], smJ[32][65];
    __shared__ int ridxI[32], ridxJ[32];
    int tid = threadIdx.x;
    if (tid < 32)      { int i = bi * 32 + tid;      ridxI[tid] = (i < NPRE) ? g_idx500[i] : -1; }
    else if (tid < 64) { int t2 = tid - 32; int j = bj * 32 + t2; ridxJ[t2] = (j < NPRE) ? g_idx500[j] : -1; }
    __syncthreads();
    int tj = tid & 31;
    int ti0 = (tid >> 5) * 4;
    int acc[4] = {0, 0, 0, 0};
    for (int w0 = 0; w0 < 512; w0 += 64) {
        for (int t = tid; t < 32 * 64; t += 256) {
            int r = t >> 6, c = t & 63;
            int mi = ridxI[r];
            smI[r][c] = (mi >= 0) ? g_masks[mi * 512 + w0 + c] : 0u;
            int mj = ridxJ[r];
            smJ[r][c] = (mj >= 0) ? g_masks[mj * 512 + w0 + c] : 0u;
        }
        __syncthreads();
#pragma unroll 8
        for (int w = 0; w < 64; ++w) {
            unsigned b = smJ[tj][w];
#pragma unroll
            for (int r = 0; r < 4; ++r) acc[r] += __popc(smI[ti0 + r][w] & b);
        }
        __syncthreads();
    }
#pragma unroll
    for (int r = 0; r < 4; ++r) {
        int i = bi * 32 + ti0 + r;
        int j = bj * 32 + tj;
        if (i < j && j < NPRE) {
            float inter = (float)acc[r];
            float uni = g_sm500[i] + g_sm500[j] - inter;
            g_iou[j * NPAD + i] = inter / fmaxf(uni, 1.f);
        }
    }
}

// ---------------- comp2 ----------------
__global__ __launch_bounds__(256) void comp_kernel() {
    int warp = threadIdx.x >> 5, lane = threadIdx.x & 31;
    int x = blockIdx.x * 8 + warp;
    if (x >= NPAD) return;
    float mx = 0.f;
    for (int i = lane; i < NPAD; i += 32) mx = fmaxf(mx, g_iou[x * NPAD + i]);
    for (int off = 16; off; off >>= 1)
        mx = fmaxf(mx, __shfl_down_sync(0xffffffffu, mx, off));
    if (lane == 0) g_comp2[x] = mx * mx;
}

// ---------------- decay ----------------
__global__ __launch_bounds__(256) void decay_kernel() {
    int warp = threadIdx.x >> 5, lane = threadIdx.x & 31;
    int j = blockIdx.x * 8 + warp;
    if (j >= NPAD) return;
    if (j >= NPRE) { if (lane == 0) g_nms[j] = -1.f; return; }
    float mn = 3.4e38f;
    for (int i = lane; i < NPRE; i += 32) {
        float v = g_iou[j * NPAD + i];
        mn = fminf(mn, g_comp2[i] - v * v);
    }
    for (int off = 16; off; off >>= 1)
        mn = fminf(mn, __shfl_down_sync(0xffffffffu, mn, off));
    if (lane == 0) {
        float ns = g_vals500[j] * expf(2.f * mn);
        g_nms[j] = (ns >= 0.05f) ? ns : 0.f;
    }
}

// ---------------- top-30 ----------------
__global__ __launch_bounds__(256) void top30_kernel(float* out) {
    __shared__ float sv[512];
    __shared__ int   si[512];
    int t = threadIdx.x;
    for (int i = t; i < 512; i += 256) { sv[i] = g_nms[i]; si[i] = i; }
    __syncthreads();
    for (int k = 2; k <= 512; k <<= 1) {
        for (int j = k >> 1; j > 0; j >>= 1) {
            for (int i = t; i < 512; i += 256) {
                int ixj = i ^ j;
                if (ixj > i) {
                    bool dir = ((i & k) == 0);
                    float v1 = sv[i], v2 = sv[ixj];
                    int  i1 = si[i], i2 = si[ixj];
                    bool before = (v1 > v2) || (v1 == v2 && i1 < i2);
                    if (before != dir) { sv[i] = v2; sv[ixj] = v1; si[i] = i2; si[ixj] = i1; }
                }
            }
            __syncthreads();
        }
    }
    if (t < MAXI) {
        float v = sv[t];
        g_fs30[t] = v;
        int id = g_idx500[si[t]];
        if (id < 0 || id >= MPAD) id = 0;
        g_sel30[t] = id;
        out[120 + t] = v;
        out[150 + t] = (v > 0.3f) ? 1.f : 0.f;
    }
}

// ---------------- recompute fp32 seg_preds for 30 selected cells ----------------
__global__ __launch_bounds__(128) void selpred_kernel(const float* __restrict__ seg) {
    __shared__ int   sidx[MAXI];
    __shared__ float kv[MAXI][EDIM];
    int tid = threadIdx.x;
    if (tid < MAXI) sidx[tid] = g_sel30[tid];
    __syncthreads();
    for (int t = tid; t < MAXI * EDIM; t += 128) {
        int c = t >> 7, e = t & 127;
        kv[c][e] = g_kernels[sidx[c] * EDIM + e];
    }
    __syncthreads();
    int p = blockIdx.x * 128 + tid;
    float acc[MAXI];
#pragma unroll
    for (int c = 0; c < MAXI; ++c) acc[c] = 0.f;
#pragma unroll 4
    for (int e = 0; e < EDIM; ++e) {
        float s = seg[e * HW + p];
#pragma unroll
        for (int c = 0; c < MAXI; ++c) acc[c] = fmaf(kv[c][e], s, acc[c]);
    }
#pragma unroll
    for (int c = 0; c < MAXI; ++c)
        g_selpred[c * HW + p] = 1.f / (1.f + expf(-acc[c]));
}

// ---------------- bilinear 4x upsample + bbox reduce ----------------
__global__ void box_kernel() {
    int n = blockIdx.x;
    int band = blockIdx.y;
    int tid = threadIdx.x;
    const float* sp = g_selpred + n * HW;
    int mnx = 512, mny = 512, mxx = -1, mxy = -1;
    for (int t = 0; t < 128; ++t) {
        int pix = band * 32768 + t * 256 + tid;
        int y = pix >> 9, x = pix & 511;
        float xin = (x + 0.5f) * 0.25f - 0.5f;
        float yin = (y + 0.5f) * 0.25f - 0.5f;
        int x0 = (int)floorf(xin); float fx = xin - (float)x0;
        int y0 = (int)floorf(yin); float fy = yin - (float)y0;
        int x0c = max(x0, 0), x1c = min(x0 + 1, 127);
        int y0c = max(y0, 0), y1c = min(y0 + 1, 127);
        float v00 = sp[y0c * 128 + x0c], v01 = sp[y0c * 128 + x1c];
        float v10 = sp[y1c * 128 + x0c], v11 = sp[y1c * 128 + x1c];
        float v = (1.f - fy) * ((1.f - fx) * v00 + fx * v01)
                +        fy  * ((1.f - fx) * v10 + fx * v11);
        if (v > 0.5f) {
            mnx = min(mnx, x); mxx = max(mxx, x);
            mny = min(mny, y); mxy = max(mxy, y);
        }
    }
    mnx = __reduce_min_sync(0xffffffffu, mnx);
    mny = __reduce_min_sync(0xffffffffu, mny);
    mxx = __reduce_max_sync(0xffffffffu, mxx);
    mxy = __reduce_max_sync(0xffffffffu, mxy);
    if ((tid & 31) == 0) {
        atomicMin(&g_box[n * 4 + 0], mnx);
        atomicMin(&g_box[n * 4 + 1], mny);
        atomicMax(&g_box[n * 4 + 2], mxx);
        atomicMax(&g_box[n * 4 + 3], mxy);
    }
}

// ---------------- finalize ----------------
__global__ void final_kernel(float* out) {
    int t = threadIdx.x;
    if (t >= MAXI) return;
    bool vis = g_fs30[t] > 0.3f;
    out[t * 4 + 0] = vis ? (float)g_box[t * 4 + 0] : 0.f;
    out[t * 4 + 1] = vis ? (float)g_box[t * 4 + 1] : 0.f;
    out[t * 4 + 2] = vis ? (float)g_box[t * 4 + 2] : 0.f;
    out[t * 4 + 3] = vis ? (float)g_box[t * 4 + 3] : 0.f;
}

// ---------------- host launcher ----------------
extern "C" void kernel_launch(void* const* d_in, const int* in_sizes, int n_in,
                              void* d_out, int out_size) {
    (void)out_size;
    Ptrs p;
    if (n_in >= 11 && in_sizes[1] == 204800) {
        for (int i = 0; i < 5; ++i) {
            p.cate[i] = (const float*)d_in[2 * i];
            p.kern[i] = (const float*)d_in[2 * i + 1];
        }
    } else {
        for (int i = 0; i < 5; ++i) {
            p.cate[i] = (const float*)d_in[i];
            p.kern[i] = (const float*)d_in[5 + i];
        }
    }
    p.seg = (const float*)d_in[10];
    float* out = (float*)d_out;

    const int GEMM_SMEM = 96 * 1024;
    cudaFuncSetAttribute(gemm_kernel, cudaFuncAttributeMaxDynamicSharedMemorySize, GEMM_SMEM);

    init_kernel<<<1024, 256>>>();
    compact_kernel<<<1, 1024>>>(p);
    gather_kernel<<<(MPAD * EDIM + 255) / 256, 256>>>(p);
    gemm_kernel<<<dim3(NCHUNK, 61), 256, GEMM_SMEM>>>(p.seg);
    cscore_kernel<<<16, 256>>>();
    top500_kernel<<<1, 1024>>>();
    nms_inter_kernel<<<dim3(16, 16), 256>>>();
    comp_kernel<<<64, 256>>>();
    decay_kernel<<<64, 256>>>();
    top30_kernel<<<1, 256>>>(out);
    selpred_kernel<<<128, 128>>>(p.seg);
    box_kernel<<<dim3(30, 8), 256>>>();
    final_kernel<<<1, 32>>>(out);
}

// round 4
// speedup vs baseline: 1.8453x; 1.0044x over previous
#include <cuda_runtime.h>
#include <math.h>

#define M_TOT 3872
#define MPAD  3904
#define EDIM  128
#define HW    16384
#define NPRE  500
#define NPAD  512
#define MAXI  30
#define NCHUNK 64            // pixel chunks of 256

// ---------------- device scratch ----------------
__device__ int      g_count;
__device__ int      g_orig[MPAD];
__device__ float    g_scores[MPAD];
__device__ float    g_kernels[MPAD * EDIM];       // compact [c][e]
__device__ float    g_kernelsT[EDIM * MPAD];      // compact [e][c]
__device__ unsigned g_masks[4096 * 512];
__device__ float    g_sumpart[MPAD * NCHUNK];
__device__ int      g_cntpart[MPAD * NCHUNK];
__device__ float    g_cscores[4096];
__device__ float    g_summask[4096];
__device__ float    g_vals500[NPAD];
__device__ int      g_idx500[NPAD];
__device__ float    g_sm500[NPAD];
__device__ float    g_iou[NPAD * NPAD];           // transposed [j][i]
__device__ float    g_comp2[NPAD];
__device__ float    g_nms[NPAD];
__device__ float    g_fs30[MAXI];
__device__ int      g_sel30[MAXI];
__device__ float    g_selpred[MAXI * HW];
__device__ int      g_box[MAXI * 4];

struct Ptrs {
    const float* cate[5];
    const float* kern[5];
    const float* seg;
};

__device__ __forceinline__ void cell_level(int m, int& l, int& ml, int& gg) {
    if      (m < 1600) { l = 0; ml = m;        gg = 1600; }
    else if (m < 2896) { l = 1; ml = m - 1600; gg = 1296; }
    else if (m < 3472) { l = 2; ml = m - 2896; gg = 576;  }
    else if (m < 3728) { l = 3; ml = m - 3472; gg = 256;  }
    else               { l = 4; ml = m - 3728; gg = 144;  }
}

__device__ __forceinline__ void cp16(void* s, const void* g) {
    unsigned sa = (unsigned)__cvta_generic_to_shared(s);
    asm volatile("cp.async.ca.shared.global [%0], [%1], 16;" :: "r"(sa), "l"(g));
}
__device__ __forceinline__ void cp_commit() { asm volatile("cp.async.commit_group;"); }
template<int N> __device__ __forceinline__ void cp_wait() {
    asm volatile("cp.async.wait_group %0;" :: "n"(N));
}

// ---------------- init ----------------
__global__ void init_kernel() {
    int id = blockIdx.x * blockDim.x + threadIdx.x;
    if (id < NPAD * NPAD) g_iou[id] = 0.f;
    if (id < MAXI) {
        g_box[id * 4 + 0] = 512;
        g_box[id * 4 + 1] = 512;
        g_box[id * 4 + 2] = -1;
        g_box[id * 4 + 3] = -1;
    }
}

// ---------------- deterministic compaction (score > 0.3) ----------------
__global__ __launch_bounds__(1024) void compact_kernel(Ptrs p) {
    __shared__ int wsum[32];
    int t = threadIdx.x;
    float sc[4]; int vf[4]; int cnt = 0;
#pragma unroll
    for (int r = 0; r < 4; ++r) {
        int m = t * 4 + r;
        float s = 0.f; int v = 0;
        if (m < M_TOT) {
            int l, ml, gg; cell_level(m, l, ml, gg);
            s = p.cate[l][ml];
            v = (s > 0.3f) ? 1 : 0;
        }
        sc[r] = s; vf[r] = v; cnt += v;
    }
    int lane = t & 31, warp = t >> 5;
    int x = cnt;
#pragma unroll
    for (int off = 1; off < 32; off <<= 1) {
        int y = __shfl_up_sync(0xffffffffu, x, off);
        if (lane >= off) x += y;
    }
    if (lane == 31) wsum[warp] = x;
    __syncthreads();
    if (warp == 0) {
        int w = wsum[lane];
#pragma unroll
        for (int off = 1; off < 32; off <<= 1) {
            int y = __shfl_up_sync(0xffffffffu, w, off);
            if (lane >= off) w += y;
        }
        wsum[lane] = w;
        if (lane == 31) g_count = w;
    }
    __syncthreads();
    int base = (warp ? wsum[warp - 1] : 0) + x - cnt;
#pragma unroll
    for (int r = 0; r < 4; ++r) {
        if (vf[r]) {
            g_orig[base] = t * 4 + r;
            g_scores[base] = sc[r];
            base++;
        }
    }
}

// ---------------- gather kernels (compact, both layouts) ----------------
__global__ void gather_kernel(Ptrs p) {
    int gid = blockIdx.x * blockDim.x + threadIdx.x;
    if (gid >= MPAD * EDIM) return;
    int c = gid >> 7;
    int e = gid & 127;
    if (c >= g_count) return;
    int m = g_orig[c];
    int l, ml, gg; cell_level(m, l, ml, gg);
    float v = p.kern[l][e * gg + ml];
    g_kernels[c * EDIM + e] = v;
    g_kernelsT[e * MPAD + c] = v;
}

// ---------------- fused GEMM (f32x2, cp.async pipelined) ----------------
// grid (64 chunks of 256 px, 61 m-tiles), 256 threads, 96KB dyn smem.
// A resident [128][64] f32 (32KB). B double-buffered [2][32][256] (64KB).
// Lane tp owns pixel pair (2tp, 2tp+1) within each 64-px group j.
__global__ __launch_bounds__(256, 2) void gemm_kernel(const float* __restrict__ seg) {
    extern __shared__ float smem[];
    float* Asm = smem;                 // [128][64]
    float* Bsm[2] = { smem + 8192, smem + 16384 };

    int Mc = g_count;
    int m0 = blockIdx.y * 64;
    if (m0 >= Mc) return;
    int tid = threadIdx.x;
    int tp = tid & 31;
    int tm = tid >> 5;
    int cb = tm * 8;
    int pchunk = blockIdx.x;
    int p0 = pchunk * 256;

    // prologue fills: A (once) + B(kc=0) as group G0
#pragma unroll
    for (int r = 0; r < 8; ++r) {
        int t = tid + r * 256;
        int k = t >> 4, c4 = (t & 15) << 2;
        cp16(Asm + k * 64 + c4, &g_kernelsT[k * MPAD + m0 + c4]);
    }
#pragma unroll
    for (int r = 0; r < 8; ++r) {
        int t = tid + r * 256;
        int kk = t >> 6, f4 = (t & 63) << 2;
        cp16(Bsm[0] + kk * 256 + f4, seg + kk * HW + p0 + f4);
    }
    cp_commit();

    unsigned long long acc[8][4];
#pragma unroll
    for (int i = 0; i < 8; ++i)
#pragma unroll
        for (int j = 0; j < 4; ++j) acc[i][j] = 0ULL;

    for (int kc = 0; kc < 4; ++kc) {
        __syncthreads();                       // prev compute done before refill
        if (kc < 3) {
#pragma unroll
            for (int r = 0; r < 8; ++r) {
                int t = tid + r * 256;
                int kk = t >> 6, f4 = (t & 63) << 2;
                cp16(Bsm[(kc + 1) & 1] + kk * 256 + f4,
                     seg + ((kc + 1) * 32 + kk) * HW + p0 + f4);
            }
            cp_commit();
            cp_wait<1>();                      // G(kc) done, G(kc+1) in flight
        } else {
            cp_wait<0>();
        }
        __syncthreads();

        const float* Bp = Bsm[kc & 1];
#pragma unroll 4
        for (int kk = 0; kk < 32; ++kk) {
            const float* ar = Asm + (kc * 32 + kk) * 64 + cb;
            float4 aA = *reinterpret_cast<const float4*>(ar);
            float4 aB = *reinterpret_cast<const float4*>(ar + 4);
            unsigned long long a64[8];
            asm("mov.b64 %0,{%1,%1};" : "=l"(a64[0]) : "f"(aA.x));
            asm("mov.b64 %0,{%1,%1};" : "=l"(a64[1]) : "f"(aA.y));
            asm("mov.b64 %0,{%1,%1};" : "=l"(a64[2]) : "f"(aA.z));
            asm("mov.b64 %0,{%1,%1};" : "=l"(a64[3]) : "f"(aA.w));
            asm("mov.b64 %0,{%1,%1};" : "=l"(a64[4]) : "f"(aB.x));
            asm("mov.b64 %0,{%1,%1};" : "=l"(a64[5]) : "f"(aB.y));
            asm("mov.b64 %0,{%1,%1};" : "=l"(a64[6]) : "f"(aB.z));
            asm("mov.b64 %0,{%1,%1};" : "=l"(a64[7]) : "f"(aB.w));
            unsigned long long b64[4];
#pragma unroll
            for (int j = 0; j < 4; ++j)
                b64[j] = *reinterpret_cast<const unsigned long long*>(
                    Bp + kk * 256 + j * 64 + tp * 2);
#pragma unroll
            for (int i = 0; i < 8; ++i)
#pragma unroll
                for (int j = 0; j < 4; ++j)
                    asm("fma.rn.f32x2 %0, %1, %2, %0;"
                        : "+l"(acc[i][j]) : "l"(a64[i]), "l"(b64[j]));
        }
    }

    // epilogue: sigmoid, bitpack (even-pixel word, odd-pixel word), per-cell sums
#pragma unroll
    for (int i = 0; i < 8; ++i) {
        int m = m0 + cb + i;
        float lsum = 0.f;
        int lcnt = 0;
#pragma unroll
        for (int j = 0; j < 4; ++j) {
            float2 v = *reinterpret_cast<float2*>(&acc[i][j]);
            float px = __frcp_rn(1.f + __expf(-v.x));
            float py = __frcp_rn(1.f + __expf(-v.y));
            bool mx = px > 0.5f, my = py > 0.5f;
            unsigned wx = __ballot_sync(0xffffffffu, mx);
            unsigned wy = __ballot_sync(0xffffffffu, my);
            if (mx) lsum += px;
            if (my) lsum += py;
            if (tp == 0) {
                lcnt += __popc(wx) + __popc(wy);
                if (m < Mc) {
                    g_masks[m * 512 + pchunk * 8 + 2 * j]     = wx;
                    g_masks[m * 512 + pchunk * 8 + 2 * j + 1] = wy;
                }
            }
        }
        for (int off = 16; off; off >>= 1)
            lsum += __shfl_down_sync(0xffffffffu, lsum, off);
        if (tp == 0 && m < Mc) {
            g_sumpart[m * NCHUNK + pchunk] = lsum;
            g_cntpart[m * NCHUNK + pchunk] = lcnt;
        }
    }
}

// ---------------- cate-score combine ----------------
__global__ void cscore_kernel() {
    int m = blockIdx.x * blockDim.x + threadIdx.x;
    if (m >= 4096) return;
    int Mc = g_count;
    if (m >= Mc) { g_cscores[m] = -1.f; g_summask[m] = 0.f; return; }
    float s = 0.f; int c = 0;
    for (int k = 0; k < NCHUNK; ++k) {
        s += g_sumpart[m * NCHUNK + k];
        c += g_cntpart[m * NCHUNK + k];
    }
    float cnt = (float)c;
    g_summask[m] = cnt;
    int om = g_orig[m];
    float stride = (om < 1600) ? 4.f : (om < 2896) ? 8.f : (om < 3472) ? 16.f : (om < 3728) ? 32.f : 64.f;
    bool keep = cnt > stride;
    float segscore = s / fmaxf(cnt, 1.f);
    g_cscores[m] = keep ? g_scores[m] * segscore : 0.f;
}

// ---------------- top-500 (bitonic over 4096) ----------------
__global__ __launch_bounds__(1024) void top500_kernel() {
    __shared__ float sv[4096];
    __shared__ int   si[4096];
    int t = threadIdx.x;
    for (int i = t; i < 4096; i += 1024) { sv[i] = g_cscores[i]; si[i] = i; }
    __syncthreads();
    for (int k = 2; k <= 4096; k <<= 1) {
        for (int j = k >> 1; j > 0; j >>= 1) {
            for (int i = t; i < 4096; i += 1024) {
                int ixj = i ^ j;
                if (ixj > i) {
                    bool dir = ((i & k) == 0);
                    float v1 = sv[i], v2 = sv[ixj];
                    int  i1 = si[i], i2 = si[ixj];
                    bool before = (v1 > v2) || (v1 == v2 && i1 < i2);
                    if (before != dir) { sv[i] = v2; sv[ixj] = v1; si[i] = i2; si[ixj] = i1; }
                }
            }
            __syncthreads();
        }
    }
    int Mc = g_count;
    for (int i = t; i < NPAD; i += 1024) {
        g_vals500[i] = sv[i];
        g_idx500[i]  = si[i];
        int cell = si[i];
        g_sm500[i] = (i < NPRE && cell < Mc) ? g_summask[cell] : 0.f;
    }
}

// ---------------- pairwise IoU via bitmask popcount (transposed store) ----------------
__global__ __launch_bounds__(256) void nms_inter_kernel() {
    int bi = blockIdx.y, bj = blockIdx.x;
    if (bi > bj) return;
    __shared__ unsigned smI[32][65], smJ[32][65];
    __shared__ int ridxI[32], ridxJ[32];
    int tid = threadIdx.x;
    if (tid < 32)      { int i = bi * 32 + tid;      ridxI[tid] = (i < NPRE) ? g_idx500[i] : -1; }
    else if (tid < 64) { int t2 = tid - 32; int j = bj * 32 + t2; ridxJ[t2] = (j < NPRE) ? g_idx500[j] : -1; }
    __syncthreads();
    int tj = tid & 31;
    int ti0 = (tid >> 5) * 4;
    int acc[4] = {0, 0, 0, 0};
    for (int w0 = 0; w0 < 512; w0 += 64) {
        for (int t = tid; t < 32 * 64; t += 256) {
            int r = t >> 6, c = t & 63;
            int mi = ridxI[r];
            smI[r][c] = (mi >= 0) ? g_masks[mi * 512 + w0 + c] : 0u;
            int mj = ridxJ[r];
            smJ[r][c] = (mj >= 0) ? g_masks[mj * 512 + w0 + c] : 0u;
        }
        __syncthreads();
#pragma unroll 8
        for (int w = 0; w < 64; ++w) {
            unsigned b = smJ[tj][w];
#pragma unroll
            for (int r = 0; r < 4; ++r) acc[r] += __popc(smI[ti0 + r][w] & b);
        }
        __syncthreads();
    }
#pragma unroll
    for (int r = 0; r < 4; ++r) {
        int i = bi * 32 + ti0 + r;
        int j = bj * 32 + tj;
        if (i < j && j < NPRE) {
            float inter = (float)acc[r];
            float uni = g_sm500[i] + g_sm500[j] - inter;
            g_iou[j * NPAD + i] = inter / fmaxf(uni, 1.f);
        }
    }
}

// ---------------- comp2 ----------------
__global__ __launch_bounds__(256) void comp_kernel() {
    int warp = threadIdx.x >> 5, lane = threadIdx.x & 31;
    int x = blockIdx.x * 8 + warp;
    if (x >= NPAD) return;
    float mx = 0.f;
    for (int i = lane; i < NPAD; i += 32) mx = fmaxf(mx, g_iou[x * NPAD + i]);
    for (int off = 16; off; off >>= 1)
        mx = fmaxf(mx, __shfl_down_sync(0xffffffffu, mx, off));
    if (lane == 0) g_comp2[x] = mx * mx;
}

// ---------------- decay ----------------
__global__ __launch_bounds__(256) void decay_kernel() {
    int warp = threadIdx.x >> 5, lane = threadIdx.x & 31;
    int j = blockIdx.x * 8 + warp;
    if (j >= NPAD) return;
    if (j >= NPRE) { if (lane == 0) g_nms[j] = -1.f; return; }
    float mn = 3.4e38f;
    for (int i = lane; i < NPRE; i += 32) {
        float v = g_iou[j * NPAD + i];
        mn = fminf(mn, g_comp2[i] - v * v);
    }
    for (int off = 16; off; off >>= 1)
        mn = fminf(mn, __shfl_down_sync(0xffffffffu, mn, off));
    if (lane == 0) {
        float ns = g_vals500[j] * expf(2.f * mn);
        g_nms[j] = (ns >= 0.05f) ? ns : 0.f;
    }
}

// ---------------- top-30 ----------------
__global__ __launch_bounds__(256) void top30_kernel(float* out) {
    __shared__ float sv[512];
    __shared__ int   si[512];
    int t = threadIdx.x;
    for (int i = t; i < 512; i += 256) { sv[i] = g_nms[i]; si[i] = i; }
    __syncthreads();
    for (int k = 2; k <= 512; k <<= 1) {
        for (int j = k >> 1; j > 0; j >>= 1) {
            for (int i = t; i < 512; i += 256) {
                int ixj = i ^ j;
                if (ixj > i) {
                    bool dir = ((i & k) == 0);
                    float v1 = sv[i], v2 = sv[ixj];
                    int  i1 = si[i], i2 = si[ixj];
                    bool before = (v1 > v2) || (v1 == v2 && i1 < i2);
                    if (before != dir) { sv[i] = v2; sv[ixj] = v1; si[i] = i2; si[ixj] = i1; }
                }
            }
            __syncthreads();
        }
    }
    if (t < MAXI) {
        float v = sv[t];
        g_fs30[t] = v;
        int id = g_idx500[si[t]];
        if (id < 0 || id >= MPAD) id = 0;
        g_sel30[t] = id;
        out[120 + t] = v;
        out[150 + t] = (v > 0.3f) ? 1.f : 0.f;
    }
}

// ---------------- recompute fp32 seg_preds for 30 selected cells ----------------
__global__ __launch_bounds__(128) void selpred_kernel(const float* __restrict__ seg) {
    __shared__ int   sidx[MAXI];
    __shared__ float kv[MAXI][EDIM];
    int tid = threadIdx.x;
    if (tid < MAXI) sidx[tid] = g_sel30[tid];
    __syncthreads();
    for (int t = tid; t < MAXI * EDIM; t += 128) {
        int c = t >> 7, e = t & 127;
        kv[c][e] = g_kernels[sidx[c] * EDIM + e];
    }
    __syncthreads();
    int p = blockIdx.x * 128 + tid;
    float acc[MAXI];
#pragma unroll
    for (int c = 0; c < MAXI; ++c) acc[c] = 0.f;
#pragma unroll 4
    for (int e = 0; e < EDIM; ++e) {
        float s = seg[e * HW + p];
#pragma unroll
        for (int c = 0; c < MAXI; ++c) acc[c] = fmaf(kv[c][e], s, acc[c]);
    }
#pragma unroll
    for (int c = 0; c < MAXI; ++c)
        g_selpred[c * HW + p] = 1.f / (1.f + expf(-acc[c]));
}

// ---------------- bilinear 4x upsample + bbox reduce ----------------
__global__ void box_kernel() {
    int n = blockIdx.x;
    int band = blockIdx.y;
    int tid = threadIdx.x;
    const float* sp = g_selpred + n * HW;
    int mnx = 512, mny = 512, mxx = -1, mxy = -1;
    for (int t = 0; t < 128; ++t) {
        int pix = band * 32768 + t * 256 + tid;
        int y = pix >> 9, x = pix & 511;
        float xin = (x + 0.5f) * 0.25f - 0.5f;
        float yin = (y + 0.5f) * 0.25f - 0.5f;
        int x0 = (int)floorf(xin); float fx = xin - (float)x0;
        int y0 = (int)floorf(yin); float fy = yin - (float)y0;
        int x0c = max(x0, 0), x1c = min(x0 + 1, 127);
        int y0c = max(y0, 0), y1c = min(y0 + 1, 127);
        float v00 = sp[y0c * 128 + x0c], v01 = sp[y0c * 128 + x1c];
        float v10 = sp[y1c * 128 + x0c], v11 = sp[y1c * 128 + x1c];
        float v = (1.f - fy) * ((1.f - fx) * v00 + fx * v01)
                +        fy  * ((1.f - fx) * v10 + fx * v11);
        if (v > 0.5f) {
            mnx = min(mnx, x); mxx = max(mxx, x);
            mny = min(mny, y); mxy = max(mxy, y);
        }
    }
    mnx = __reduce_min_sync(0xffffffffu, mnx);
    mny = __reduce_min_sync(0xffffffffu, mny);
    mxx = __reduce_max_sync(0xffffffffu, mxx);
    mxy = __reduce_max_sync(0xffffffffu, mxy);
    if ((tid & 31) == 0) {
        atomicMin(&g_box[n * 4 + 0], mnx);
        atomicMin(&g_box[n * 4 + 1], mny);
        atomicMax(&g_box[n * 4 + 2], mxx);
        atomicMax(&g_box[n * 4 + 3], mxy);
    }
}

// ---------------- finalize ----------------
__global__ void final_kernel(float* out) {
    int t = threadIdx.x;
    if (t >= MAXI) return;
    bool vis = g_fs30[t] > 0.3f;
    out[t * 4 + 0] = vis ? (float)g_box[t * 4 + 0] : 0.f;
    out[t * 4 + 1] = vis ? (float)g_box[t * 4 + 1] : 0.f;
    out[t * 4 + 2] = vis ? (float)g_box[t * 4 + 2] : 0.f;
    out[t * 4 + 3] = vis ? (float)g_box[t * 4 + 3] : 0.f;
}

// ---------------- host launcher ----------------
extern "C" void kernel_launch(void* const* d_in, const int* in_sizes, int n_in,
                              void* d_out, int out_size) {
    (void)out_size;
    Ptrs p;
    if (n_in >= 11 && in_sizes[1] == 204800) {
        for (int i = 0; i < 5; ++i) {
            p.cate[i] = (const float*)d_in[2 * i];
            p.kern[i] = (const float*)d_in[2 * i + 1];
        }
    } else {
        for (int i = 0; i < 5; ++i) {
            p.cate[i] = (const float*)d_in[i];
            p.kern[i] = (const float*)d_in[5 + i];
        }
    }
    p.seg = (const float*)d_in[10];
    float* out = (float*)d_out;

    const int GEMM_SMEM = 96 * 1024;
    cudaFuncSetAttribute(gemm_kernel, cudaFuncAttributeMaxDynamicSharedMemorySize, GEMM_SMEM);

    init_kernel<<<1024, 256>>>();
    compact_kernel<<<1, 1024>>>(p);
    gather_kernel<<<(MPAD * EDIM + 255) / 256, 256>>>(p);
    gemm_kernel<<<dim3(NCHUNK, 61), 256, GEMM_SMEM>>>(p.seg);
    cscore_kernel<<<16, 256>>>();
    top500_kernel<<<1, 1024>>>();
    nms_inter_kernel<<<dim3(16, 16), 256>>>();
    comp_kernel<<<64, 256>>>();
    decay_kernel<<<64, 256>>>();
    top30_kernel<<<1, 256>>>(out);
    selpred_kernel<<<128, 128>>>(p.seg);
    box_kernel<<<dim3(30, 8), 256>>>();
    final_kernel<<<1, 32>>>(out);
}